// round 1
// baseline (speedup 1.0000x reference)
#include <cuda_runtime.h>

// Problem constants (fixed by the reference)
#define BB   32
#define SS   512
#define HH   768
#define NC   32
#define MHL  16
#define TPB  192          // HH / 4 threads, one float4 each
#define H4   (HH / 4)     // 192

__global__ __launch_bounds__(TPB)
void bert_emb_kernel(
    const int*    __restrict__ input_ids,       // [B,S]
    const int*    __restrict__ header_ids,      // [B,NC,MHL]
    const int*    __restrict__ token_type_ids,  // [B,S]
    const int*    __restrict__ match_type_ids,  // [B,S]
    const int*    __restrict__ type_idx,        // [B,S]
    const int*    __restrict__ col_pos,         // [B,NC]
    const int*    __restrict__ col_idx,         // [B,NC]
    const int*    __restrict__ header_len,      // [B,NC]
    const float4* __restrict__ word_emb,        // [VOCAB,H4]
    const float4* __restrict__ pos_emb,         // [MAX_POS,H4]
    const float4* __restrict__ tok_type_emb,    // [2,H4]
    const float4* __restrict__ match_emb,       // [11,H4]
    const float4* __restrict__ type_emb,        // [6,H4]
    const float4* __restrict__ ln_w,            // [H4]
    const float4* __restrict__ ln_b,            // [H4]
    float4*       __restrict__ out)             // [B,S,H4]
{
    const int row = blockIdx.x;      // b*S + s
    const int b   = row >> 9;        // row / 512
    const int s   = row & (SS - 1);  // row % 512
    const int tid = threadIdx.x;

    __shared__ int   sh_c;
    __shared__ float sh_sum[8];
    __shared__ float sh_sq[8];
    __shared__ float sh_stats[2];

    if (tid == 0) sh_c = -1;
    __syncthreads();
    // col_pos entries are distinct within a batch row -> at most one writer
    if (tid < NC && col_pos[b * NC + tid] == s) sh_c = tid;
    __syncthreads();

    // ---- base vector: either word embedding or pooled header embedding ----
    float4 v;
    const int c = sh_c;
    bool use_pool = false;
    int cidx = 0, len = 0;
    if (c >= 0) {
        cidx = col_idx[b * NC + c];
        len  = header_len[b * NC + cidx];
        use_pool = (len > 0);
    }

    if (use_pool) {
        float4 acc = make_float4(0.f, 0.f, 0.f, 0.f);
        const int* hids = header_ids + (b * NC + cidx) * MHL;
        for (int l = 0; l < len; ++l) {
            const int wid = hids[l];
            const float4 w = word_emb[(size_t)wid * H4 + tid];
            acc.x += w.x; acc.y += w.y; acc.z += w.z; acc.w += w.w;
        }
        const float inv = 1.0f / (float)len;
        v.x = acc.x * inv; v.y = acc.y * inv;
        v.z = acc.z * inv; v.w = acc.w * inv;
    } else {
        const int wid = input_ids[row];
        v = word_emb[(size_t)wid * H4 + tid];
    }

    // ---- add positional / type embeddings ----
    const int tt = token_type_ids[row];
    const int mt = match_type_ids[row];
    const int ty = type_idx[row];

    const float4 p = pos_emb[s * H4 + tid];
    const float4 t = tok_type_emb[tt * H4 + tid];
    const float4 m = match_emb[mt * H4 + tid];
    const float4 y = type_emb[ty * H4 + tid];

    v.x += p.x + t.x + m.x + y.x;
    v.y += p.y + t.y + m.y + y.y;
    v.z += p.z + t.z + m.z + y.z;
    v.w += p.w + t.w + m.w + y.w;

    // ---- LayerNorm (single pass: sum + sumsq) ----
    float sum = v.x + v.y + v.z + v.w;
    float sq  = v.x * v.x + v.y * v.y + v.z * v.z + v.w * v.w;

    #pragma unroll
    for (int o = 16; o > 0; o >>= 1) {
        sum += __shfl_down_sync(0xffffffffu, sum, o);
        sq  += __shfl_down_sync(0xffffffffu, sq,  o);
    }
    const int warp = tid >> 5;
    const int lane = tid & 31;
    if (lane == 0) { sh_sum[warp] = sum; sh_sq[warp] = sq; }
    __syncthreads();

    if (tid == 0) {
        float ts = 0.f, tq = 0.f;
        #pragma unroll
        for (int i = 0; i < TPB / 32; ++i) { ts += sh_sum[i]; tq += sh_sq[i]; }
        const float mean = ts * (1.0f / HH);
        float var = tq * (1.0f / HH) - mean * mean;
        var = fmaxf(var, 0.0f);
        sh_stats[0] = mean;
        sh_stats[1] = rsqrtf(var + 1e-12f);
    }
    __syncthreads();

    const float mean = sh_stats[0];
    const float rstd = sh_stats[1];
    const float4 gw = ln_w[tid];
    const float4 gb = ln_b[tid];

    float4 o;
    o.x = (v.x - mean) * rstd * gw.x + gb.x;
    o.y = (v.y - mean) * rstd * gw.y + gb.y;
    o.z = (v.z - mean) * rstd * gw.z + gb.z;
    o.w = (v.w - mean) * rstd * gw.w + gb.w;

    out[(size_t)row * H4 + tid] = o;
}

extern "C" void kernel_launch(void* const* d_in, const int* in_sizes, int n_in,
                              void* d_out, int out_size) {
    (void)in_sizes; (void)n_in; (void)out_size;
    const int*    input_ids       = (const int*)   d_in[0];
    const int*    header_ids      = (const int*)   d_in[1];
    const int*    token_type_ids  = (const int*)   d_in[2];
    const int*    match_type_ids  = (const int*)   d_in[3];
    const int*    type_idx        = (const int*)   d_in[4];
    const int*    col_pos         = (const int*)   d_in[5];
    const int*    col_idx         = (const int*)   d_in[6];
    const int*    header_len      = (const int*)   d_in[7];
    const float4* word_emb        = (const float4*)d_in[8];
    const float4* pos_emb         = (const float4*)d_in[9];
    const float4* tok_type_emb    = (const float4*)d_in[10];
    const float4* match_emb       = (const float4*)d_in[11];
    const float4* type_emb        = (const float4*)d_in[12];
    const float4* ln_w            = (const float4*)d_in[13];
    const float4* ln_b            = (const float4*)d_in[14];
    float4*       out             = (float4*)d_out;

    bert_emb_kernel<<<BB * SS, TPB>>>(
        input_ids, header_ids, token_type_ids, match_type_ids, type_idx,
        col_pos, col_idx, header_len, word_emb, pos_emb, tok_type_emb,
        match_emb, type_emb, ln_w, ln_b, out);
}

// round 2
// speedup vs baseline: 1.1209x; 1.1209x over previous
#include <cuda_runtime.h>

#define BB   32
#define SS   512
#define HH   768
#define NC   32
#define MHL  16
#define TPB  192
#define H4   (HH / 4)     // 192
#define RPC  8            // rows per CTA
#define NCOMB (2 * 11 * 6) // 132

__device__ float4 g_comb[NCOMB * H4];   // tok+match+type combined table

__global__ __launch_bounds__(TPB)
void build_comb_kernel(const float4* __restrict__ tok_type_emb,
                       const float4* __restrict__ match_emb,
                       const float4* __restrict__ type_emb)
{
    const int combo = blockIdx.x;          // 0..131
    const int tt  = combo / 66;
    const int rem = combo % 66;
    const int mt  = rem / 6;
    const int ty  = rem % 6;
    const int tid = threadIdx.x;

    const float4 a = tok_type_emb[tt * H4 + tid];
    const float4 b = match_emb[mt * H4 + tid];
    const float4 c = type_emb[ty * H4 + tid];
    float4 r;
    r.x = a.x + b.x + c.x;
    r.y = a.y + b.y + c.y;
    r.z = a.z + b.z + c.z;
    r.w = a.w + b.w + c.w;
    g_comb[combo * H4 + tid] = r;
}

__global__ __launch_bounds__(TPB)
void bert_emb_kernel(
    const int*    __restrict__ input_ids,       // [B,S]
    const int*    __restrict__ header_ids,      // [B,NC,MHL]
    const int*    __restrict__ token_type_ids,  // [B,S]
    const int*    __restrict__ match_type_ids,  // [B,S]
    const int*    __restrict__ type_idx,        // [B,S]
    const int*    __restrict__ col_pos,         // [B,NC]
    const int*    __restrict__ col_idx,         // [B,NC]
    const int*    __restrict__ header_len,      // [B,NC]
    const float4* __restrict__ word_emb,        // [VOCAB,H4]
    const float4* __restrict__ pos_emb,         // [MAX_POS,H4]
    const float4* __restrict__ ln_w,            // [H4]
    const float4* __restrict__ ln_b,            // [H4]
    float4*       __restrict__ out)             // [B,S,H4]
{
    const int cta = blockIdx.x;                 // B * S / RPC = 2048
    const int b   = cta / (SS / RPC);
    const int s0  = (cta % (SS / RPC)) * RPC;
    const int tid = threadIdx.x;
    const int warp = tid >> 5;
    const int lane = tid & 31;

    __shared__ int   sh_c[RPC];
    __shared__ float sh_sum[2][8];
    __shared__ float sh_sq[2][8];

    // per-CTA constants
    const float4 gw = ln_w[tid];
    const float4 gb = ln_b[tid];

    // resolve which rows in [s0, s0+RPC) are column-scatter targets
    if (tid < RPC) sh_c[tid] = -1;
    __syncthreads();
    if (tid < NC) {
        const int cp = col_pos[b * NC + tid];
        if (cp >= s0 && cp < s0 + RPC) sh_c[cp - s0] = tid;
    }
    __syncthreads();

    #pragma unroll 1
    for (int j = 0; j < RPC; ++j) {
        const int s   = s0 + j;
        const int row = b * SS + s;
        const int p   = j & 1;

        // ---- base vector ----
        const int c = sh_c[j];
        float4 v;
        bool use_pool = false;
        int len = 0;
        const int* hids = nullptr;
        if (c >= 0) {
            const int cidx = col_idx[b * NC + c];
            len = header_len[b * NC + cidx];
            use_pool = (len > 0);
            hids = header_ids + (b * NC + cidx) * MHL;
        }

        if (use_pool) {
            float4 acc = make_float4(0.f, 0.f, 0.f, 0.f);
            for (int l = 0; l < len; ++l) {
                const float4 w = word_emb[(size_t)hids[l] * H4 + tid];
                acc.x += w.x; acc.y += w.y; acc.z += w.z; acc.w += w.w;
            }
            const float inv = 1.0f / (float)len;
            v.x = acc.x * inv; v.y = acc.y * inv;
            v.z = acc.z * inv; v.w = acc.w * inv;
        } else {
            v = word_emb[(size_t)input_ids[row] * H4 + tid];
        }

        // ---- add positional + combined small-table ----
        const int combo = token_type_ids[row] * 66
                        + match_type_ids[row] * 6
                        + type_idx[row];
        const float4 pe = pos_emb[s * H4 + tid];
        const float4 cb = g_comb[combo * H4 + tid];

        v.x += pe.x + cb.x;
        v.y += pe.y + cb.y;
        v.z += pe.z + cb.z;
        v.w += pe.w + cb.w;

        // ---- LayerNorm reduce (single pass) ----
        float sum = v.x + v.y + v.z + v.w;
        float sq  = v.x * v.x + v.y * v.y + v.z * v.z + v.w * v.w;
        #pragma unroll
        for (int o = 16; o > 0; o >>= 1) {
            sum += __shfl_down_sync(0xffffffffu, sum, o);
            sq  += __shfl_down_sync(0xffffffffu, sq,  o);
        }
        if (lane == 0) { sh_sum[p][warp] = sum; sh_sq[p][warp] = sq; }
        __syncthreads();

        float ts = 0.f, tq = 0.f;
        #pragma unroll
        for (int i = 0; i < TPB / 32; ++i) { ts += sh_sum[p][i]; tq += sh_sq[p][i]; }
        const float mean = ts * (1.0f / HH);
        float var = tq * (1.0f / HH) - mean * mean;
        var = fmaxf(var, 0.0f);
        const float rstd = rsqrtf(var + 1e-12f);

        float4 o;
        o.x = (v.x - mean) * rstd * gw.x + gb.x;
        o.y = (v.y - mean) * rstd * gw.y + gb.y;
        o.z = (v.z - mean) * rstd * gw.z + gb.z;
        o.w = (v.w - mean) * rstd * gw.w + gb.w;

        __stcs(&out[(size_t)row * H4 + tid], o);
    }
}

extern "C" void kernel_launch(void* const* d_in, const int* in_sizes, int n_in,
                              void* d_out, int out_size) {
    (void)in_sizes; (void)n_in; (void)out_size;
    const int*    input_ids       = (const int*)   d_in[0];
    const int*    header_ids      = (const int*)   d_in[1];
    const int*    token_type_ids  = (const int*)   d_in[2];
    const int*    match_type_ids  = (const int*)   d_in[3];
    const int*    type_idx        = (const int*)   d_in[4];
    const int*    col_pos         = (const int*)   d_in[5];
    const int*    col_idx         = (const int*)   d_in[6];
    const int*    header_len      = (const int*)   d_in[7];
    const float4* word_emb        = (const float4*)d_in[8];
    const float4* pos_emb         = (const float4*)d_in[9];
    const float4* tok_type_emb    = (const float4*)d_in[10];
    const float4* match_emb       = (const float4*)d_in[11];
    const float4* type_emb        = (const float4*)d_in[12];
    const float4* ln_w            = (const float4*)d_in[13];
    const float4* ln_b            = (const float4*)d_in[14];
    float4*       out             = (float4*)d_out;

    build_comb_kernel<<<NCOMB, TPB>>>(tok_type_emb, match_emb, type_emb);
    bert_emb_kernel<<<(BB * SS) / RPC, TPB>>>(
        input_ids, header_ids, token_type_ids, match_type_ids, type_idx,
        col_pos, col_idx, header_len, word_emb, pos_emb, ln_w, ln_b, out);
}

// round 3
// speedup vs baseline: 1.3540x; 1.2079x over previous
#include <cuda_runtime.h>

#define BB   32
#define SS   512
#define HH   768
#define NC   32
#define MHL  16
#define H4   (HH / 4)       // 192 float4 per row
#define CPL  6              // float4 chunks per lane (192/32)
#define TPB  256            // 8 warps
#define RPW  8              // rows per warp
#define NCOMB (2 * 11 * 6)  // 132

__device__ float4 g_comb[NCOMB * H4];

__global__ __launch_bounds__(192)
void build_comb_kernel(const float4* __restrict__ tok_type_emb,
                       const float4* __restrict__ match_emb,
                       const float4* __restrict__ type_emb)
{
    const int combo = blockIdx.x;          // 0..131
    const int tt  = combo / 66;
    const int rem = combo % 66;
    const int mt  = rem / 6;
    const int ty  = rem % 6;
    const int tid = threadIdx.x;

    const float4 a = tok_type_emb[tt * H4 + tid];
    const float4 b = match_emb[mt * H4 + tid];
    const float4 c = type_emb[ty * H4 + tid];
    float4 r;
    r.x = a.x + b.x + c.x;
    r.y = a.y + b.y + c.y;
    r.z = a.z + b.z + c.z;
    r.w = a.w + b.w + c.w;
    g_comb[combo * H4 + tid] = r;
}

__global__ __launch_bounds__(TPB, 2)
void bert_emb_kernel(
    const int*    __restrict__ input_ids,       // [B,S]
    const int*    __restrict__ header_ids,      // [B,NC,MHL]
    const int*    __restrict__ token_type_ids,  // [B,S]
    const int*    __restrict__ match_type_ids,  // [B,S]
    const int*    __restrict__ type_idx,        // [B,S]
    const int*    __restrict__ col_pos,         // [B,NC]
    const int*    __restrict__ col_idx,         // [B,NC]
    const int*    __restrict__ header_len,      // [B,NC]
    const float4* __restrict__ word_emb,        // [VOCAB,H4]
    const float4* __restrict__ pos_emb,         // [MAX_POS,H4]
    const float4* __restrict__ ln_w,            // [H4]
    const float4* __restrict__ ln_b,            // [H4]
    float4*       __restrict__ out)             // [B,S,H4]
{
    const int tid  = threadIdx.x;
    const int warp = tid >> 5;
    const int lane = tid & 31;

    __shared__ float4 sgw[H4];
    __shared__ float4 sgb[H4];
    if (tid < H4) {
        sgw[tid] = ln_w[tid];
        sgb[tid] = ln_b[tid];
    }
    __syncthreads();

    // global warp id -> block of RPW consecutive rows (same batch: 8 | 512)
    const int gw_id = blockIdx.x * (TPB / 32) + warp;
    const int row0  = gw_id * RPW;
    const int b     = row0 >> 9;

    // per-warp batch metadata, one lane each (NC == 32)
    const int cp = col_pos[b * NC + lane];
    const int ci = col_idx[b * NC + lane];
    const int hl = header_len[b * NC + lane];

    #pragma unroll 1
    for (int r = 0; r < RPW; ++r) {
        const int row = row0 + r;
        const int s   = row & (SS - 1);

        // ---- column-scatter detection (register-only) ----
        const unsigned mmask = __ballot_sync(0xffffffffu, cp == s);
        int len = 0, cidx = 0;
        if (mmask) {
            const int c = __ffs(mmask) - 1;
            cidx = __shfl_sync(0xffffffffu, ci, c);
            len  = __shfl_sync(0xffffffffu, hl, cidx);
        }

        // ---- base vector: word embedding or pooled header ----
        float4 v[CPL];
        if (len > 0) {
            #pragma unroll
            for (int k = 0; k < CPL; ++k) v[k] = make_float4(0.f, 0.f, 0.f, 0.f);
            const int* hids = header_ids + (b * NC + cidx) * MHL;
            for (int l = 0; l < len; ++l) {
                const size_t base = (size_t)hids[l] * H4 + lane;
                #pragma unroll
                for (int k = 0; k < CPL; ++k) {
                    const float4 w = word_emb[base + k * 32];
                    v[k].x += w.x; v[k].y += w.y; v[k].z += w.z; v[k].w += w.w;
                }
            }
            const float inv = 1.0f / (float)len;
            #pragma unroll
            for (int k = 0; k < CPL; ++k) {
                v[k].x *= inv; v[k].y *= inv; v[k].z *= inv; v[k].w *= inv;
            }
        } else {
            const size_t base = (size_t)input_ids[row] * H4 + lane;
            #pragma unroll
            for (int k = 0; k < CPL; ++k) v[k] = word_emb[base + k * 32];
        }

        // ---- add positional + combined small-table ----
        const int combo = token_type_ids[row] * 66
                        + match_type_ids[row] * 6
                        + type_idx[row];
        const size_t pbase = (size_t)s * H4 + lane;
        const size_t cbase = (size_t)combo * H4 + lane;
        #pragma unroll
        for (int k = 0; k < CPL; ++k) {
            const float4 pe = pos_emb[pbase + k * 32];
            const float4 cb = g_comb[cbase + k * 32];
            v[k].x += pe.x + cb.x;
            v[k].y += pe.y + cb.y;
            v[k].z += pe.z + cb.z;
            v[k].w += pe.w + cb.w;
        }

        // ---- LayerNorm: warp-only reduce (no barriers) ----
        float sum = 0.f, sq = 0.f;
        #pragma unroll
        for (int k = 0; k < CPL; ++k) {
            sum += v[k].x + v[k].y + v[k].z + v[k].w;
            sq  += v[k].x * v[k].x + v[k].y * v[k].y
                 + v[k].z * v[k].z + v[k].w * v[k].w;
        }
        #pragma unroll
        for (int o = 16; o > 0; o >>= 1) {
            sum += __shfl_xor_sync(0xffffffffu, sum, o);
            sq  += __shfl_xor_sync(0xffffffffu, sq,  o);
        }
        const float mean = sum * (1.0f / HH);
        float var = sq * (1.0f / HH) - mean * mean;
        var = fmaxf(var, 0.0f);
        const float rstd = rsqrtf(var + 1e-12f);

        float4* orow = out + (size_t)row * H4 + lane;
        #pragma unroll
        for (int k = 0; k < CPL; ++k) {
            const float4 gwv = sgw[lane + k * 32];
            const float4 gbv = sgb[lane + k * 32];
            float4 o;
            o.x = (v[k].x - mean) * rstd * gwv.x + gbv.x;
            o.y = (v[k].y - mean) * rstd * gwv.y + gbv.y;
            o.z = (v[k].z - mean) * rstd * gwv.z + gbv.z;
            o.w = (v[k].w - mean) * rstd * gwv.w + gbv.w;
            __stcs(orow + k * 32, o);
        }
    }
}

extern "C" void kernel_launch(void* const* d_in, const int* in_sizes, int n_in,
                              void* d_out, int out_size) {
    (void)in_sizes; (void)n_in; (void)out_size;
    const int*    input_ids       = (const int*)   d_in[0];
    const int*    header_ids      = (const int*)   d_in[1];
    const int*    token_type_ids  = (const int*)   d_in[2];
    const int*    match_type_ids  = (const int*)   d_in[3];
    const int*    type_idx        = (const int*)   d_in[4];
    const int*    col_pos         = (const int*)   d_in[5];
    const int*    col_idx         = (const int*)   d_in[6];
    const int*    header_len      = (const int*)   d_in[7];
    const float4* word_emb        = (const float4*)d_in[8];
    const float4* pos_emb         = (const float4*)d_in[9];
    const float4* tok_type_emb    = (const float4*)d_in[10];
    const float4* match_emb       = (const float4*)d_in[11];
    const float4* type_emb        = (const float4*)d_in[12];
    const float4* ln_w            = (const float4*)d_in[13];
    const float4* ln_b            = (const float4*)d_in[14];
    float4*       out             = (float4*)d_out;

    build_comb_kernel<<<NCOMB, 192>>>(tok_type_emb, match_emb, type_emb);

    const int n_warp_rows = (BB * SS) / RPW;          // 2048 warps needed
    const int grid = n_warp_rows / (TPB / 32);        // 256 CTAs
    bert_emb_kernel<<<grid, TPB>>>(
        input_ids, header_ids, token_type_ids, match_type_ids, type_idx,
        col_pos, col_idx, header_len, word_emb, pos_emb, ln_w, ln_b, out);
}